// round 7
// baseline (speedup 1.0000x reference)
#include <cuda_runtime.h>
#include <cuda_bf16.h>
#include <math.h>
#include <cstdint>

// ---------------------------------------------------------------------------
// Problem constants
// ---------------------------------------------------------------------------
#define B 8
#define SEQ 1024
#define WIN 9
#define D 512
#define DFF 1024
#define VOCAB 16384
#define NTOK (B * SEQ)   // 8192
#define EPS 1e-5f

// ---------------------------------------------------------------------------
// Scratch buffers (device globals: no allocation allowed)
// ---------------------------------------------------------------------------
__device__ float g_h0 [NTOK * D];
__device__ float g_q  [NTOK * D];
__device__ float g_k  [NTOK * D];
__device__ float g_v  [NTOK * D];
__device__ float g_att[NTOK * D];
__device__ float g_o  [NTOK * D];
__device__ float g_h1 [NTOK * D];
__device__ float g_mid[NTOK * DFF];
__device__ float g_f  [NTOK * D];
__device__ float g_h2 [NTOK * D];
// transposed weights ([N,K] K-major, values pre-rounded to tf32)
__device__ float g_WqT[D * D];
__device__ float g_WkT[D * D];
__device__ float g_WvT[D * D];
__device__ float g_WoT[D * D];
__device__ float g_W1T[DFF * D];
__device__ float g_W2T[D * DFF];
__device__ float g_WhT[VOCAB * D];

// ---------------------------------------------------------------------------
// tf32 / cp.async / ldmatrix helpers (all plain compute_103-legal PTX)
// ---------------------------------------------------------------------------
__device__ __forceinline__ uint32_t cvt_tf32(float f) {
    uint32_t r;
    asm("cvt.rna.tf32.f32 %0, %1;" : "=r"(r) : "f"(f));
    return r;
}
__device__ __forceinline__ float round_tf32(float f) {
    return __uint_as_float(cvt_tf32(f));
}
__device__ __forceinline__ uint32_t smem_to_u32(const void* p) {
    uint32_t a;
    asm("{ .reg .u64 t; cvta.to.shared.u64 t, %1; cvt.u32.u64 %0, t; }" : "=r"(a) : "l"(p));
    return a;
}
__device__ __forceinline__ void cp_async16(uint32_t saddr, const void* gptr) {
    asm volatile("cp.async.cg.shared.global [%0], [%1], 16;" :: "r"(saddr), "l"(gptr));
}
#define CP_COMMIT()  asm volatile("cp.async.commit_group;" ::: "memory")
#define CP_WAIT(n)   asm volatile("cp.async.wait_group %0;" :: "n"(n) : "memory")

__device__ __forceinline__ void ldsm_x4(uint32_t* d, uint32_t addr) {
    asm volatile("ldmatrix.sync.aligned.m8n8.x4.shared.b16 {%0,%1,%2,%3}, [%4];"
        : "=r"(d[0]), "=r"(d[1]), "=r"(d[2]), "=r"(d[3]) : "r"(addr));
}

__device__ __forceinline__ void mma_tf32(float* d, const uint32_t* a, const uint32_t* b) {
    asm volatile(
        "mma.sync.aligned.m16n8k8.row.col.f32.tf32.tf32.f32 "
        "{%0,%1,%2,%3}, {%4,%5,%6,%7}, {%8,%9}, {%0,%1,%2,%3};"
        : "+f"(d[0]), "+f"(d[1]), "+f"(d[2]), "+f"(d[3])
        : "r"(a[0]), "r"(a[1]), "r"(a[2]), "r"(a[3]),
          "r"(b[0]), "r"(b[1]));
}

// ---------------------------------------------------------------------------
// Kernel: weight transpose + tf32 round   in[R][Cn] -> out[Cn][R]
// ---------------------------------------------------------------------------
__global__ void transpose_kernel(const float* __restrict__ in, float* __restrict__ out,
                                 int R, int Cn) {
    __shared__ float t[32][33];
    int bx = blockIdx.x * 32, by = blockIdx.y * 32;
    int x = bx + threadIdx.x;
    int y = by + threadIdx.y;
#pragma unroll
    for (int i = 0; i < 32; i += 8)
        t[threadIdx.y + i][threadIdx.x] = in[(size_t)(y + i) * Cn + x];
    __syncthreads();
    x = by + threadIdx.x;
    y = bx + threadIdx.y;
#pragma unroll
    for (int i = 0; i < 32; i += 8)
        out[(size_t)(y + i) * R + x] = round_tf32(t[threadIdx.x][threadIdx.y + i]);
}

// ---------------------------------------------------------------------------
// Kernel: tf32 mma.sync GEMM  C[M,N] = A[M,K] @ Bt[N,K]^T + bias (+ReLU)(+round)
// CTA tile 256x128, BK=32, 256 threads (8 warps 4x2), warp tile 64x64.
// 4-stage cp.async pipeline, XOR-swizzled SMEM, ldmatrix.x4 fragment loads.
// ---------------------------------------------------------------------------
#define GBM 256
#define GBN 128
#define GBK 32
#define STAGES 4
#define STAGE_AU (GBM * 32)          // uint32s per A stage
#define STAGE_BU (GBN * 32)          // uint32s per B stage
#define STAGE_AB (STAGE_AU * 4)      // bytes
#define STAGE_BB (STAGE_BU * 4)

__global__ __launch_bounds__(256, 1) void gemm_tc(
    const float* __restrict__ A, const float* __restrict__ Bt,
    const float* __restrict__ bias, float* __restrict__ C,
    int M, int N, int K, int relu, int round_out)
{
    extern __shared__ uint32_t smem[];
    const uint32_t sA_u32 = smem_to_u32(smem);
    const uint32_t sB_u32 = sA_u32 + STAGES * STAGE_AB;

    const int tid  = threadIdx.x;
    const int lane = tid & 31;
    const int wid  = tid >> 5;
    const int wm   = wid >> 1;           // 0..3
    const int wn   = wid & 1;            // 0..1
    const int bm   = blockIdx.y * GBM;
    const int bn   = blockIdx.x * GBN;
    const int nk   = K >> 5;

    // cp.async per-thread coordinates (A: 8 x 16B, B: 4 x 16B per chunk)
    int ar[8], ac[8]; uint32_t aso[8];
#pragma unroll
    for (int t = 0; t < 8; t++) {
        int idx = t * 256 + tid;
        ar[t] = idx >> 3; ac[t] = idx & 7;
        aso[t] = (uint32_t)(ar[t] * 32 + ((ac[t] ^ (ar[t] & 7)) << 2)) * 4u;
    }
    int br[4], bc[4]; uint32_t bso[4];
#pragma unroll
    for (int t = 0; t < 4; t++) {
        int idx = t * 256 + tid;
        br[t] = idx >> 3; bc[t] = idx & 7;
        bso[t] = (uint32_t)(br[t] * 32 + ((bc[t] ^ (br[t] & 7)) << 2)) * 4u;
    }

    // ldmatrix per-thread row constants
    // A x4: lanes 0-15 -> rows (lane&15) of the 16-row group, k_lo; lanes 16-31 same rows, k_hi
    uint32_t aRowB[4], aR7[4];
#pragma unroll
    for (int mf = 0; mf < 4; mf++) {
        int r = wm * 64 + mf * 16 + (lane & 15);
        aRowB[mf] = (uint32_t)r * 128u;
        aR7[mf]   = (uint32_t)(r & 7);
    }
    const uint32_t gselA = (lane >> 4) & 1;
    // B x4 (two nf per load): lanes 0-7 rows 0-7 k_lo; 8-15 rows 0-7 k_hi;
    //                         16-23 rows 8-15 k_lo; 24-31 rows 8-15 k_hi
    uint32_t bRowB[4], bR7[4];
#pragma unroll
    for (int np = 0; np < 4; np++) {
        int r = wn * 64 + np * 16 + (lane & 7) + ((lane >> 4) << 3);
        bRowB[np] = (uint32_t)r * 128u;
        bR7[np]   = (uint32_t)(r & 7);
    }
    const uint32_t gselB = (lane >> 3) & 1;

    float acc[4][8][4];
#pragma unroll
    for (int i = 0; i < 4; i++)
#pragma unroll
        for (int j = 0; j < 8; j++)
#pragma unroll
            for (int l = 0; l < 4; l++) acc[i][j][l] = 0.0f;

#define LOAD_STAGE(chunk, stage) do { \
    const int _kc = (chunk) << 5; \
    const uint32_t _sa = sA_u32 + (uint32_t)(stage) * STAGE_AB; \
    const uint32_t _sb = sB_u32 + (uint32_t)(stage) * STAGE_BB; \
    _Pragma("unroll") \
    for (int _t = 0; _t < 8; _t++) \
        cp_async16(_sa + aso[_t], A + (size_t)(bm + ar[_t]) * K + _kc + ac[_t] * 4); \
    _Pragma("unroll") \
    for (int _t = 0; _t < 4; _t++) \
        cp_async16(_sb + bso[_t], Bt + (size_t)(bn + br[_t]) * K + _kc + bc[_t] * 4); \
    CP_COMMIT(); \
} while (0)

    // prologue: stages 0..2   (nk >= 16 at every call site)
    LOAD_STAGE(0, 0);
    LOAD_STAGE(1, 1);
    LOAD_STAGE(2, 2);

    for (int chunk = 0; chunk < nk; chunk++) {
        CP_WAIT(STAGES - 2);
        __syncthreads();

        if (chunk + STAGES - 1 < nk) {
            LOAD_STAGE(chunk + STAGES - 1, (chunk + STAGES - 1) & (STAGES - 1));
        } else {
            CP_COMMIT();
        }

        const uint32_t saBase = sA_u32 + (uint32_t)(chunk & (STAGES - 1)) * STAGE_AB;
        const uint32_t sbBase = sB_u32 + (uint32_t)(chunk & (STAGES - 1)) * STAGE_BB;

#pragma unroll
        for (int ks = 0; ks < 4; ks++) {
            const uint32_t gA = 2 * ks + gselA;
            const uint32_t gB = 2 * ks + gselB;
            uint32_t af[4][4];
#pragma unroll
            for (int mf = 0; mf < 4; mf++)
                ldsm_x4(af[mf], saBase + aRowB[mf] + ((gA ^ aR7[mf]) << 4));
            uint32_t bq[4][4];
#pragma unroll
            for (int np = 0; np < 4; np++)
                ldsm_x4(bq[np], sbBase + bRowB[np] + ((gB ^ bR7[np]) << 4));
#pragma unroll
            for (int mf = 0; mf < 4; mf++)
#pragma unroll
                for (int nf = 0; nf < 8; nf++)
                    mma_tf32(acc[mf][nf], af[mf], &bq[nf >> 1][(nf & 1) * 2]);
        }
    }

    // ---- epilogue ----
#pragma unroll
    for (int mf = 0; mf < 4; mf++) {
        int row0 = bm + wm * 64 + mf * 16 + (lane >> 2);
#pragma unroll
        for (int nf = 0; nf < 8; nf++) {
            int col = bn + wn * 64 + nf * 8 + (lane & 3) * 2;
            float bx = bias[col], by = bias[col + 1];
            float2 v0, v1;
            v0.x = acc[mf][nf][0] + bx; v0.y = acc[mf][nf][1] + by;
            v1.x = acc[mf][nf][2] + bx; v1.y = acc[mf][nf][3] + by;
            if (relu) {
                v0.x = fmaxf(v0.x, 0.0f); v0.y = fmaxf(v0.y, 0.0f);
                v1.x = fmaxf(v1.x, 0.0f); v1.y = fmaxf(v1.y, 0.0f);
            }
            if (round_out) {
                v0.x = round_tf32(v0.x); v0.y = round_tf32(v0.y);
                v1.x = round_tf32(v1.x); v1.y = round_tf32(v1.y);
            }
            *(float2*)(C + (size_t)row0 * N + col)       = v0;
            *(float2*)(C + (size_t)(row0 + 8) * N + col) = v1;
        }
    }
}

// ---------------------------------------------------------------------------
// Kernel: embedding gather + 2D positional encoding (output tf32-rounded)
// ---------------------------------------------------------------------------
__global__ void embed_kernel(const int* __restrict__ x,
                             const float* __restrict__ tab,
                             const float* __restrict__ rowe,
                             const float* __restrict__ cole,
                             float* __restrict__ h) {
    int qi = blockIdx.x;
    int s  = qi & (SEQ - 1);
    int r  = s >> 5, c = s & 31;
    int tok = x[qi];
    int d = threadIdx.x * 4;

    float4 e = *(const float4*)&tab[(size_t)tok * D + d];
    float4 p;
    if (d < D / 2) p = *(const float4*)&rowe[r * (D / 2) + d];
    else           p = *(const float4*)&cole[c * (D / 2) + (d - D / 2)];
    e.x = round_tf32(e.x + p.x); e.y = round_tf32(e.y + p.y);
    e.z = round_tf32(e.z + p.z); e.w = round_tf32(e.w + p.w);
    *(float4*)&h[(size_t)qi * D + d] = e;
}

// ---------------------------------------------------------------------------
// Kernel: fused local-causal attention (<=181 keys; output tf32-rounded)
// ---------------------------------------------------------------------------
__global__ void attn_kernel(const float* __restrict__ Q,
                            const float* __restrict__ K,
                            const float* __restrict__ V,
                            float* __restrict__ O) {
    int qi = blockIdx.x;
    int b = qi >> 10, s = qi & (SEQ - 1);
    int r = s >> 5, c = s & 31;
    int r0 = (r - WIN < 0) ? 0 : r - WIN;
    int c0 = (c - WIN < 0) ? 0 : c - WIN;
    int c1 = (c + WIN > 31) ? 31 : c + WIN;
    int wcols = c1 - c0 + 1;
    int nfull = r - r0;
    int nk = nfull * wcols + (c - c0 + 1);

    __shared__ float qv[D];
    __shared__ float sc[256];
    __shared__ int   kid[256];
    __shared__ float red[4];

    int tid = threadIdx.x;
    int lane = tid & 31, wid = tid >> 5;

    *(float4*)&qv[tid * 4] = *(const float4*)&Q[(size_t)qi * D + tid * 4];
    __syncthreads();

    const float scale = 0.044194173824159216f;
    const float* kbase = K + (size_t)b * SEQ * D;

    for (int j = wid; j < nk; j += 4) {
        int row, col;
        if (j < nfull * wcols) { row = r0 + j / wcols; col = c0 + j % wcols; }
        else                   { row = r;             col = c0 + (j - nfull * wcols); }
        int kk = row * 32 + col;
        const float* krow = kbase + (size_t)kk * D;
        float sum = 0.0f;
#pragma unroll
        for (int t = 0; t < D / 32; t++)
            sum = fmaf(qv[lane + 32 * t], krow[lane + 32 * t], sum);
#pragma unroll
        for (int off = 16; off; off >>= 1)
            sum += __shfl_xor_sync(0xffffffffu, sum, off);
        if (lane == 0) { sc[j] = sum * scale; kid[j] = kk; }
    }
    __syncthreads();

    float m = -1e30f;
    for (int j = tid; j < nk; j += 128) m = fmaxf(m, sc[j]);
#pragma unroll
    for (int off = 16; off; off >>= 1)
        m = fmaxf(m, __shfl_xor_sync(0xffffffffu, m, off));
    if (lane == 0) red[wid] = m;
    __syncthreads();
    m = fmaxf(fmaxf(red[0], red[1]), fmaxf(red[2], red[3]));

    float ssum = 0.0f;
    for (int j = tid; j < nk; j += 128) {
        float e = __expf(sc[j] - m);
        sc[j] = e;
        ssum += e;
    }
    __syncthreads();
#pragma unroll
    for (int off = 16; off; off >>= 1)
        ssum += __shfl_xor_sync(0xffffffffu, ssum, off);
    if (lane == 0) red[wid] = ssum;
    __syncthreads();
    float inv = 1.0f / (red[0] + red[1] + red[2] + red[3]);

    const float* vbase = V + (size_t)b * SEQ * D;
    int d = tid * 4;
    float4 acc = make_float4(0.f, 0.f, 0.f, 0.f);
    for (int j = 0; j < nk; j++) {
        float w = sc[j] * inv;
        float4 v = *(const float4*)&vbase[(size_t)kid[j] * D + d];
        acc.x = fmaf(w, v.x, acc.x);
        acc.y = fmaf(w, v.y, acc.y);
        acc.z = fmaf(w, v.z, acc.z);
        acc.w = fmaf(w, v.w, acc.w);
    }
    acc.x = round_tf32(acc.x); acc.y = round_tf32(acc.y);
    acc.z = round_tf32(acc.z); acc.w = round_tf32(acc.w);
    *(float4*)&O[(size_t)qi * D + d] = acc;
}

// ---------------------------------------------------------------------------
// Kernel: out = LayerNorm(X + Y) * g + b   (output tf32-rounded)
// ---------------------------------------------------------------------------
__global__ void add_ln_kernel(const float* __restrict__ X,
                              const float* __restrict__ Y,
                              const float* __restrict__ g,
                              const float* __restrict__ beta,
                              float* __restrict__ out) {
    int row = blockIdx.x;
    int tid = threadIdx.x;
    int lane = tid & 31, wid = tid >> 5;
    __shared__ float reds[4], redq[4];

    int d = tid * 4;
    float4 xv = *(const float4*)&X[(size_t)row * D + d];
    float4 yv = *(const float4*)&Y[(size_t)row * D + d];
    xv.x += yv.x; xv.y += yv.y; xv.z += yv.z; xv.w += yv.w;

    float s  = xv.x + xv.y + xv.z + xv.w;
    float sq = xv.x * xv.x + xv.y * xv.y + xv.z * xv.z + xv.w * xv.w;
#pragma unroll
    for (int off = 16; off; off >>= 1) {
        s  += __shfl_xor_sync(0xffffffffu, s,  off);
        sq += __shfl_xor_sync(0xffffffffu, sq, off);
    }
    if (lane == 0) { reds[wid] = s; redq[wid] = sq; }
    __syncthreads();
    s  = reds[0] + reds[1] + reds[2] + reds[3];
    sq = redq[0] + redq[1] + redq[2] + redq[3];

    float mu  = s * (1.0f / D);
    float var = sq * (1.0f / D) - mu * mu;
    float rstd = rsqrtf(var + EPS);

    float4 gv = *(const float4*)&g[d];
    float4 bv = *(const float4*)&beta[d];
    float4 o;
    o.x = round_tf32((xv.x - mu) * rstd * gv.x + bv.x);
    o.y = round_tf32((xv.y - mu) * rstd * gv.y + bv.y);
    o.z = round_tf32((xv.z - mu) * rstd * gv.z + bv.z);
    o.w = round_tf32((xv.w - mu) * rstd * gv.w + bv.w);
    *(float4*)&out[(size_t)row * D + d] = o;
}

// ---------------------------------------------------------------------------
// Launch   (ncu -s5 -c1 captures launch index 3 => place gemm_tc there)
// ---------------------------------------------------------------------------
extern "C" void kernel_launch(void* const* d_in, const int* in_sizes, int n_in,
                              void* d_out, int out_size) {
    const int*   x     = (const int*)  d_in[0];
    const float* tab   = (const float*)d_in[1];
    const float* rowe  = (const float*)d_in[2];
    const float* cole  = (const float*)d_in[3];
    const float* Wq    = (const float*)d_in[4];
    const float* bq    = (const float*)d_in[5];
    const float* Wk    = (const float*)d_in[6];
    const float* bk    = (const float*)d_in[7];
    const float* Wv    = (const float*)d_in[8];
    const float* bv    = (const float*)d_in[9];
    const float* Wo    = (const float*)d_in[10];
    const float* bo    = (const float*)d_in[11];
    const float* ln1g  = (const float*)d_in[12];
    const float* ln1b  = (const float*)d_in[13];
    const float* W1    = (const float*)d_in[14];
    const float* b1    = (const float*)d_in[15];
    const float* W2    = (const float*)d_in[16];
    const float* b2    = (const float*)d_in[17];
    const float* ln2g  = (const float*)d_in[18];
    const float* ln2b  = (const float*)d_in[19];
    const float* Wh    = (const float*)d_in[20];
    const float* bh    = (const float*)d_in[21];
    float* out = (float*)d_out;

    float *h0, *q, *k, *v, *att, *o, *h1, *mid, *f, *h2;
    float *WqT, *WkT, *WvT, *WoT, *W1T, *W2T, *WhT;
    cudaGetSymbolAddress((void**)&h0,  g_h0);
    cudaGetSymbolAddress((void**)&q,   g_q);
    cudaGetSymbolAddress((void**)&k,   g_k);
    cudaGetSymbolAddress((void**)&v,   g_v);
    cudaGetSymbolAddress((void**)&att, g_att);
    cudaGetSymbolAddress((void**)&o,   g_o);
    cudaGetSymbolAddress((void**)&h1,  g_h1);
    cudaGetSymbolAddress((void**)&mid, g_mid);
    cudaGetSymbolAddress((void**)&f,   g_f);
    cudaGetSymbolAddress((void**)&h2,  g_h2);
    cudaGetSymbolAddress((void**)&WqT, g_WqT);
    cudaGetSymbolAddress((void**)&WkT, g_WkT);
    cudaGetSymbolAddress((void**)&WvT, g_WvT);
    cudaGetSymbolAddress((void**)&WoT, g_WoT);
    cudaGetSymbolAddress((void**)&W1T, g_W1T);
    cudaGetSymbolAddress((void**)&W2T, g_W2T);
    cudaGetSymbolAddress((void**)&WhT, g_WhT);

    const int GEMM_SMEM = STAGES * (STAGE_AU + STAGE_BU) * 4;  // 196608 bytes
    static int attr_set = 0;
    if (!attr_set) {
        cudaFuncSetAttribute(gemm_tc, cudaFuncAttributeMaxDynamicSharedMemorySize, GEMM_SMEM);
        attr_set = 1;
    }

    dim3 tb(32, 8);

    // launches 0-2
    embed_kernel<<<NTOK, 128>>>(x, tab, rowe, cole, h0);
    transpose_kernel<<<dim3(D / 32, D / 32), tb>>>(Wq, WqT, D, D);
    transpose_kernel<<<dim3(D / 32, D / 32), tb>>>(Wk, WkT, D, D);

    // launch index 3: profiled GEMM
    gemm_tc<<<dim3(D / GBN, NTOK / GBM), 256, GEMM_SMEM>>>(h0, WqT, bq, q, NTOK, D, D, 0, 0);

    transpose_kernel<<<dim3(D / 32, D / 32), tb>>>(Wv, WvT, D, D);
    gemm_tc<<<dim3(D / GBN, NTOK / GBM), 256, GEMM_SMEM>>>(h0, WkT, bk, k, NTOK, D, D, 0, 0);
    gemm_tc<<<dim3(D / GBN, NTOK / GBM), 256, GEMM_SMEM>>>(h0, WvT, bv, v, NTOK, D, D, 0, 0);

    // remaining weight transposes (before their consumers)
    transpose_kernel<<<dim3(D / 32,     D / 32),   tb>>>(Wo, WoT, D,   D);
    transpose_kernel<<<dim3(DFF / 32,   D / 32),   tb>>>(W1, W1T, D,   DFF);
    transpose_kernel<<<dim3(D / 32,     DFF / 32), tb>>>(W2, W2T, DFF, D);
    transpose_kernel<<<dim3(VOCAB / 32, D / 32),   tb>>>(Wh, WhT, D,   VOCAB);

    // fused local-causal attention
    attn_kernel<<<NTOK, 128>>>(q, k, v, att);

    // output projection
    gemm_tc<<<dim3(D / GBN, NTOK / GBM), 256, GEMM_SMEM>>>(att, WoT, bo, o, NTOK, D, D, 0, 0);

    // residual + LN1
    add_ln_kernel<<<NTOK, 128>>>(h0, o, ln1g, ln1b, h1);

    // FFN (mid output tf32-rounded: consumed by FFN2 GEMM)
    gemm_tc<<<dim3(DFF / GBN, NTOK / GBM), 256, GEMM_SMEM>>>(h1, W1T, b1, mid, NTOK, DFF, D, 1, 1);
    gemm_tc<<<dim3(D / GBN, NTOK / GBM), 256, GEMM_SMEM>>>(mid, W2T, b2, f, NTOK, D, DFF, 0, 0);

    // residual + LN2
    add_ln_kernel<<<NTOK, 128>>>(h1, f, ln2g, ln2b, h2);

    // vocab head -> d_out
    gemm_tc<<<dim3(VOCAB / GBN, NTOK / GBM), 256, GEMM_SMEM>>>(h2, WhT, bh, out, NTOK, VOCAB, D, 0, 0);
}

// round 8
// speedup vs baseline: 1.0114x; 1.0114x over previous
#include <cuda_runtime.h>
#include <cuda_bf16.h>
#include <math.h>
#include <cstdint>

// ---------------------------------------------------------------------------
// Problem constants
// ---------------------------------------------------------------------------
#define B 8
#define SEQ 1024
#define WIN 9
#define D 512
#define DFF 1024
#define VOCAB 16384
#define NTOK (B * SEQ)   // 8192
#define EPS 1e-5f

// ---------------------------------------------------------------------------
// Scratch buffers (device globals: no allocation allowed)
// ---------------------------------------------------------------------------
__device__ float g_h0 [NTOK * D];
__device__ float g_q  [NTOK * D];
__device__ float g_k  [NTOK * D];
__device__ float g_v  [NTOK * D];
__device__ float g_att[NTOK * D];
__device__ float g_o  [NTOK * D];
__device__ float g_h1 [NTOK * D];
__device__ float g_mid[NTOK * DFF];
__device__ float g_f  [NTOK * D];
__device__ float g_h2 [NTOK * D];
// transposed weights ([N,K] K-major, values pre-rounded to tf32)
__device__ float g_WqT[D * D];
__device__ float g_WkT[D * D];
__device__ float g_WvT[D * D];
__device__ float g_WoT[D * D];
__device__ float g_W1T[DFF * D];
__device__ float g_W2T[D * DFF];
__device__ float g_WhT[VOCAB * D];

// ---------------------------------------------------------------------------
// tf32 / cp.async / ldmatrix helpers (all plain compute_103-legal PTX)
// ---------------------------------------------------------------------------
__device__ __forceinline__ uint32_t cvt_tf32(float f) {
    uint32_t r;
    asm("cvt.rna.tf32.f32 %0, %1;" : "=r"(r) : "f"(f));
    return r;
}
__device__ __forceinline__ float round_tf32(float f) {
    return __uint_as_float(cvt_tf32(f));
}
__device__ __forceinline__ uint32_t smem_to_u32(const void* p) {
    uint32_t a;
    asm("{ .reg .u64 t; cvta.to.shared.u64 t, %1; cvt.u32.u64 %0, t; }" : "=r"(a) : "l"(p));
    return a;
}
__device__ __forceinline__ void cp_async16(uint32_t saddr, const void* gptr) {
    asm volatile("cp.async.cg.shared.global [%0], [%1], 16;" :: "r"(saddr), "l"(gptr));
}
#define CP_COMMIT()  asm volatile("cp.async.commit_group;" ::: "memory")
#define CP_WAIT(n)   asm volatile("cp.async.wait_group %0;" :: "n"(n) : "memory")

__device__ __forceinline__ void ldsm_x4(uint32_t* d, uint32_t addr) {
    asm volatile("ldmatrix.sync.aligned.m8n8.x4.shared.b16 {%0,%1,%2,%3}, [%4];"
        : "=r"(d[0]), "=r"(d[1]), "=r"(d[2]), "=r"(d[3]) : "r"(addr));
}

__device__ __forceinline__ void mma_tf32(float* d, const uint32_t* a, const uint32_t* b) {
    asm volatile(
        "mma.sync.aligned.m16n8k8.row.col.f32.tf32.tf32.f32 "
        "{%0,%1,%2,%3}, {%4,%5,%6,%7}, {%8,%9}, {%0,%1,%2,%3};"
        : "+f"(d[0]), "+f"(d[1]), "+f"(d[2]), "+f"(d[3])
        : "r"(a[0]), "r"(a[1]), "r"(a[2]), "r"(a[3]),
          "r"(b[0]), "r"(b[1]));
}

// ---------------------------------------------------------------------------
// Kernel: weight transpose + tf32 round   in[R][Cn] -> out[Cn][R]
// ---------------------------------------------------------------------------
__global__ void transpose_kernel(const float* __restrict__ in, float* __restrict__ out,
                                 int R, int Cn) {
    __shared__ float t[32][33];
    int bx = blockIdx.x * 32, by = blockIdx.y * 32;
    int x = bx + threadIdx.x;
    int y = by + threadIdx.y;
#pragma unroll
    for (int i = 0; i < 32; i += 8)
        t[threadIdx.y + i][threadIdx.x] = in[(size_t)(y + i) * Cn + x];
    __syncthreads();
    x = by + threadIdx.x;
    y = bx + threadIdx.y;
#pragma unroll
    for (int i = 0; i < 32; i += 8)
        out[(size_t)(y + i) * R + x] = round_tf32(t[threadIdx.x][threadIdx.y + i]);
}

// ---------------------------------------------------------------------------
// Kernel: tf32 mma.sync GEMM  C[M,N] = A[M,K] @ Bt[N,K]^T + bias (+ReLU)(+round)
// CTA tile 256x128, BK=32, 512 threads (16 warps, 4x4), warp tile 64x32.
// 4-stage cp.async pipeline, XOR-swizzled SMEM, ldmatrix.x4 fragment loads.
// ---------------------------------------------------------------------------
#define GBM 256
#define GBN 128
#define GBK 32
#define STAGES 4
#define NTHR 512
#define STAGE_AU (GBM * 32)          // uint32s per A stage
#define STAGE_BU (GBN * 32)          // uint32s per B stage
#define STAGE_AB (STAGE_AU * 4)      // bytes
#define STAGE_BB (STAGE_BU * 4)

__global__ __launch_bounds__(NTHR, 1) void gemm_tc(
    const float* __restrict__ A, const float* __restrict__ Bt,
    const float* __restrict__ bias, float* __restrict__ C,
    int M, int N, int K, int relu, int round_out)
{
    extern __shared__ uint32_t smem[];
    const uint32_t sA_u32 = smem_to_u32(smem);
    const uint32_t sB_u32 = sA_u32 + STAGES * STAGE_AB;

    const int tid  = threadIdx.x;
    const int lane = tid & 31;
    const int wid  = tid >> 5;
    const int wm   = wid >> 2;           // 0..3  (M warps, 64 rows each)
    const int wn   = wid & 3;            // 0..3  (N warps, 32 cols each)
    const int bm   = blockIdx.y * GBM;
    const int bn   = blockIdx.x * GBN;
    const int nk   = K >> 5;

    // cp.async per-thread coordinates (A: 4 x 16B, B: 2 x 16B per chunk)
    int ar[4], ac[4]; uint32_t aso[4];
#pragma unroll
    for (int t = 0; t < 4; t++) {
        int idx = t * NTHR + tid;        // 0..2047
        ar[t] = idx >> 3; ac[t] = idx & 7;
        aso[t] = (uint32_t)(ar[t] * 32 + ((ac[t] ^ (ar[t] & 7)) << 2)) * 4u;
    }
    int br[2], bc[2]; uint32_t bso[2];
#pragma unroll
    for (int t = 0; t < 2; t++) {
        int idx = t * NTHR + tid;        // 0..1023
        br[t] = idx >> 3; bc[t] = idx & 7;
        bso[t] = (uint32_t)(br[t] * 32 + ((bc[t] ^ (br[t] & 7)) << 2)) * 4u;
    }

    // ldmatrix per-thread row constants
    // A x4 per mf: lanes 0-15 rows (lane&15) of 16-row group k_lo; lanes 16-31 k_hi
    uint32_t aRowB[4], aR7[4];
#pragma unroll
    for (int mf = 0; mf < 4; mf++) {
        int r = wm * 64 + mf * 16 + (lane & 15);
        aRowB[mf] = (uint32_t)r * 128u;
        aR7[mf]   = (uint32_t)(r & 7);
    }
    const uint32_t gselA = (lane >> 4) & 1;
    // B x4 per np (2 nf per load): lanes 0-7 rows 0-7 k_lo; 8-15 k_hi; 16-23 rows 8-15 k_lo; 24-31 k_hi
    uint32_t bRowB[2], bR7[2];
#pragma unroll
    for (int np = 0; np < 2; np++) {
        int r = wn * 32 + np * 16 + (lane & 7) + ((lane >> 4) << 3);
        bRowB[np] = (uint32_t)r * 128u;
        bR7[np]   = (uint32_t)(r & 7);
    }
    const uint32_t gselB = (lane >> 3) & 1;

    float acc[4][4][4];
#pragma unroll
    for (int i = 0; i < 4; i++)
#pragma unroll
        for (int j = 0; j < 4; j++)
#pragma unroll
            for (int l = 0; l < 4; l++) acc[i][j][l] = 0.0f;

#define LOAD_STAGE(chunk, stage) do { \
    const int _kc = (chunk) << 5; \
    const uint32_t _sa = sA_u32 + (uint32_t)(stage) * STAGE_AB; \
    const uint32_t _sb = sB_u32 + (uint32_t)(stage) * STAGE_BB; \
    _Pragma("unroll") \
    for (int _t = 0; _t < 4; _t++) \
        cp_async16(_sa + aso[_t], A + (size_t)(bm + ar[_t]) * K + _kc + ac[_t] * 4); \
    _Pragma("unroll") \
    for (int _t = 0; _t < 2; _t++) \
        cp_async16(_sb + bso[_t], Bt + (size_t)(bn + br[_t]) * K + _kc + bc[_t] * 4); \
    CP_COMMIT(); \
} while (0)

    // prologue: stages 0..2   (nk >= 16 at every call site)
    LOAD_STAGE(0, 0);
    LOAD_STAGE(1, 1);
    LOAD_STAGE(2, 2);

    for (int chunk = 0; chunk < nk; chunk++) {
        CP_WAIT(STAGES - 2);
        __syncthreads();

        if (chunk + STAGES - 1 < nk) {
            LOAD_STAGE(chunk + STAGES - 1, (chunk + STAGES - 1) & (STAGES - 1));
        } else {
            CP_COMMIT();
        }

        const uint32_t saBase = sA_u32 + (uint32_t)(chunk & (STAGES - 1)) * STAGE_AB;
        const uint32_t sbBase = sB_u32 + (uint32_t)(chunk & (STAGES - 1)) * STAGE_BB;

#pragma unroll
        for (int ks = 0; ks < 4; ks++) {
            const uint32_t gA = 2 * ks + gselA;
            const uint32_t gB = 2 * ks + gselB;
            uint32_t af[4][4];
#pragma unroll
            for (int mf = 0; mf < 4; mf++)
                ldsm_x4(af[mf], saBase + aRowB[mf] + ((gA ^ aR7[mf]) << 4));
            uint32_t bq[2][4];
#pragma unroll
            for (int np = 0; np < 2; np++)
                ldsm_x4(bq[np], sbBase + bRowB[np] + ((gB ^ bR7[np]) << 4));
#pragma unroll
            for (int mf = 0; mf < 4; mf++)
#pragma unroll
                for (int nf = 0; nf < 4; nf++)
                    mma_tf32(acc[mf][nf], af[mf], &bq[nf >> 1][(nf & 1) * 2]);
        }
    }

    // ---- epilogue ----
#pragma unroll
    for (int mf = 0; mf < 4; mf++) {
        int row0 = bm + wm * 64 + mf * 16 + (lane >> 2);
#pragma unroll
        for (int nf = 0; nf < 4; nf++) {
            int col = bn + wn * 32 + nf * 8 + (lane & 3) * 2;
            float bx = bias[col], by = bias[col + 1];
            float2 v0, v1;
            v0.x = acc[mf][nf][0] + bx; v0.y = acc[mf][nf][1] + by;
            v1.x = acc[mf][nf][2] + bx; v1.y = acc[mf][nf][3] + by;
            if (relu) {
                v0.x = fmaxf(v0.x, 0.0f); v0.y = fmaxf(v0.y, 0.0f);
                v1.x = fmaxf(v1.x, 0.0f); v1.y = fmaxf(v1.y, 0.0f);
            }
            if (round_out) {
                v0.x = round_tf32(v0.x); v0.y = round_tf32(v0.y);
                v1.x = round_tf32(v1.x); v1.y = round_tf32(v1.y);
            }
            *(float2*)(C + (size_t)row0 * N + col)       = v0;
            *(float2*)(C + (size_t)(row0 + 8) * N + col) = v1;
        }
    }
}

// ---------------------------------------------------------------------------
// Kernel: embedding gather + 2D positional encoding (output tf32-rounded)
// ---------------------------------------------------------------------------
__global__ void embed_kernel(const int* __restrict__ x,
                             const float* __restrict__ tab,
                             const float* __restrict__ rowe,
                             const float* __restrict__ cole,
                             float* __restrict__ h) {
    int qi = blockIdx.x;
    int s  = qi & (SEQ - 1);
    int r  = s >> 5, c = s & 31;
    int tok = x[qi];
    int d = threadIdx.x * 4;

    float4 e = *(const float4*)&tab[(size_t)tok * D + d];
    float4 p;
    if (d < D / 2) p = *(const float4*)&rowe[r * (D / 2) + d];
    else           p = *(const float4*)&cole[c * (D / 2) + (d - D / 2)];
    e.x = round_tf32(e.x + p.x); e.y = round_tf32(e.y + p.y);
    e.z = round_tf32(e.z + p.z); e.w = round_tf32(e.w + p.w);
    *(float4*)&h[(size_t)qi * D + d] = e;
}

// ---------------------------------------------------------------------------
// Kernel: fused local-causal attention (<=181 keys; output tf32-rounded)
// ---------------------------------------------------------------------------
__global__ void attn_kernel(const float* __restrict__ Q,
                            const float* __restrict__ K,
                            const float* __restrict__ V,
                            float* __restrict__ O) {
    int qi = blockIdx.x;
    int b = qi >> 10, s = qi & (SEQ - 1);
    int r = s >> 5, c = s & 31;
    int r0 = (r - WIN < 0) ? 0 : r - WIN;
    int c0 = (c - WIN < 0) ? 0 : c - WIN;
    int c1 = (c + WIN > 31) ? 31 : c + WIN;
    int wcols = c1 - c0 + 1;
    int nfull = r - r0;
    int nk = nfull * wcols + (c - c0 + 1);

    __shared__ float qv[D];
    __shared__ float sc[256];
    __shared__ int   kid[256];
    __shared__ float red[4];

    int tid = threadIdx.x;
    int lane = tid & 31, wid = tid >> 5;

    *(float4*)&qv[tid * 4] = *(const float4*)&Q[(size_t)qi * D + tid * 4];
    __syncthreads();

    const float scale = 0.044194173824159216f;
    const float* kbase = K + (size_t)b * SEQ * D;

    for (int j = wid; j < nk; j += 4) {
        int row, col;
        if (j < nfull * wcols) { row = r0 + j / wcols; col = c0 + j % wcols; }
        else                   { row = r;             col = c0 + (j - nfull * wcols); }
        int kk = row * 32 + col;
        const float* krow = kbase + (size_t)kk * D;
        float sum = 0.0f;
#pragma unroll
        for (int t = 0; t < D / 32; t++)
            sum = fmaf(qv[lane + 32 * t], krow[lane + 32 * t], sum);
#pragma unroll
        for (int off = 16; off; off >>= 1)
            sum += __shfl_xor_sync(0xffffffffu, sum, off);
        if (lane == 0) { sc[j] = sum * scale; kid[j] = kk; }
    }
    __syncthreads();

    float m = -1e30f;
    for (int j = tid; j < nk; j += 128) m = fmaxf(m, sc[j]);
#pragma unroll
    for (int off = 16; off; off >>= 1)
        m = fmaxf(m, __shfl_xor_sync(0xffffffffu, m, off));
    if (lane == 0) red[wid] = m;
    __syncthreads();
    m = fmaxf(fmaxf(red[0], red[1]), fmaxf(red[2], red[3]));

    float ssum = 0.0f;
    for (int j = tid; j < nk; j += 128) {
        float e = __expf(sc[j] - m);
        sc[j] = e;
        ssum += e;
    }
    __syncthreads();
#pragma unroll
    for (int off = 16; off; off >>= 1)
        ssum += __shfl_xor_sync(0xffffffffu, ssum, off);
    if (lane == 0) red[wid] = ssum;
    __syncthreads();
    float inv = 1.0f / (red[0] + red[1] + red[2] + red[3]);

    const float* vbase = V + (size_t)b * SEQ * D;
    int d = tid * 4;
    float4 acc = make_float4(0.f, 0.f, 0.f, 0.f);
    for (int j = 0; j < nk; j++) {
        float w = sc[j] * inv;
        float4 v = *(const float4*)&vbase[(size_t)kid[j] * D + d];
        acc.x = fmaf(w, v.x, acc.x);
        acc.y = fmaf(w, v.y, acc.y);
        acc.z = fmaf(w, v.z, acc.z);
        acc.w = fmaf(w, v.w, acc.w);
    }
    acc.x = round_tf32(acc.x); acc.y = round_tf32(acc.y);
    acc.z = round_tf32(acc.z); acc.w = round_tf32(acc.w);
    *(float4*)&O[(size_t)qi * D + d] = acc;
}

// ---------------------------------------------------------------------------
// Kernel: out = LayerNorm(X + Y) * g + b   (output tf32-rounded)
// ---------------------------------------------------------------------------
__global__ void add_ln_kernel(const float* __restrict__ X,
                              const float* __restrict__ Y,
                              const float* __restrict__ g,
                              const float* __restrict__ beta,
                              float* __restrict__ out) {
    int row = blockIdx.x;
    int tid = threadIdx.x;
    int lane = tid & 31, wid = tid >> 5;
    __shared__ float reds[4], redq[4];

    int d = tid * 4;
    float4 xv = *(const float4*)&X[(size_t)row * D + d];
    float4 yv = *(const float4*)&Y[(size_t)row * D + d];
    xv.x += yv.x; xv.y += yv.y; xv.z += yv.z; xv.w += yv.w;

    float s  = xv.x + xv.y + xv.z + xv.w;
    float sq = xv.x * xv.x + xv.y * xv.y + xv.z * xv.z + xv.w * xv.w;
#pragma unroll
    for (int off = 16; off; off >>= 1) {
        s  += __shfl_xor_sync(0xffffffffu, s,  off);
        sq += __shfl_xor_sync(0xffffffffu, sq, off);
    }
    if (lane == 0) { reds[wid] = s; redq[wid] = sq; }
    __syncthreads();
    s  = reds[0] + reds[1] + reds[2] + reds[3];
    sq = redq[0] + redq[1] + redq[2] + redq[3];

    float mu  = s * (1.0f / D);
    float var = sq * (1.0f / D) - mu * mu;
    float rstd = rsqrtf(var + EPS);

    float4 gv = *(const float4*)&g[d];
    float4 bv = *(const float4*)&beta[d];
    float4 o;
    o.x = round_tf32((xv.x - mu) * rstd * gv.x + bv.x);
    o.y = round_tf32((xv.y - mu) * rstd * gv.y + bv.y);
    o.z = round_tf32((xv.z - mu) * rstd * gv.z + bv.z);
    o.w = round_tf32((xv.w - mu) * rstd * gv.w + bv.w);
    *(float4*)&out[(size_t)row * D + d] = o;
}

// ---------------------------------------------------------------------------
// Launch   (ncu -s5 -c1 captures launch index 3 => place gemm_tc there)
// ---------------------------------------------------------------------------
extern "C" void kernel_launch(void* const* d_in, const int* in_sizes, int n_in,
                              void* d_out, int out_size) {
    const int*   x     = (const int*)  d_in[0];
    const float* tab   = (const float*)d_in[1];
    const float* rowe  = (const float*)d_in[2];
    const float* cole  = (const float*)d_in[3];
    const float* Wq    = (const float*)d_in[4];
    const float* bq    = (const float*)d_in[5];
    const float* Wk    = (const float*)d_in[6];
    const float* bk    = (const float*)d_in[7];
    const float* Wv    = (const float*)d_in[8];
    const float* bv    = (const float*)d_in[9];
    const float* Wo    = (const float*)d_in[10];
    const float* bo    = (const float*)d_in[11];
    const float* ln1g  = (const float*)d_in[12];
    const float* ln1b  = (const float*)d_in[13];
    const float* W1    = (const float*)d_in[14];
    const float* b1    = (const float*)d_in[15];
    const float* W2    = (const float*)d_in[16];
    const float* b2    = (const float*)d_in[17];
    const float* ln2g  = (const float*)d_in[18];
    const float* ln2b  = (const float*)d_in[19];
    const float* Wh    = (const float*)d_in[20];
    const float* bh    = (const float*)d_in[21];
    float* out = (float*)d_out;

    float *h0, *q, *k, *v, *att, *o, *h1, *mid, *f, *h2;
    float *WqT, *WkT, *WvT, *WoT, *W1T, *W2T, *WhT;
    cudaGetSymbolAddress((void**)&h0,  g_h0);
    cudaGetSymbolAddress((void**)&q,   g_q);
    cudaGetSymbolAddress((void**)&k,   g_k);
    cudaGetSymbolAddress((void**)&v,   g_v);
    cudaGetSymbolAddress((void**)&att, g_att);
    cudaGetSymbolAddress((void**)&o,   g_o);
    cudaGetSymbolAddress((void**)&h1,  g_h1);
    cudaGetSymbolAddress((void**)&mid, g_mid);
    cudaGetSymbolAddress((void**)&f,   g_f);
    cudaGetSymbolAddress((void**)&h2,  g_h2);
    cudaGetSymbolAddress((void**)&WqT, g_WqT);
    cudaGetSymbolAddress((void**)&WkT, g_WkT);
    cudaGetSymbolAddress((void**)&WvT, g_WvT);
    cudaGetSymbolAddress((void**)&WoT, g_WoT);
    cudaGetSymbolAddress((void**)&W1T, g_W1T);
    cudaGetSymbolAddress((void**)&W2T, g_W2T);
    cudaGetSymbolAddress((void**)&WhT, g_WhT);

    const int GEMM_SMEM = STAGES * (STAGE_AU + STAGE_BU) * 4;  // 196608 bytes
    static int attr_set = 0;
    if (!attr_set) {
        cudaFuncSetAttribute(gemm_tc, cudaFuncAttributeMaxDynamicSharedMemorySize, GEMM_SMEM);
        attr_set = 1;
    }

    dim3 tb(32, 8);

    // launches 0-2
    embed_kernel<<<NTOK, 128>>>(x, tab, rowe, cole, h0);
    transpose_kernel<<<dim3(D / 32, D / 32), tb>>>(Wq, WqT, D, D);
    transpose_kernel<<<dim3(D / 32, D / 32), tb>>>(Wk, WkT, D, D);

    // launch index 3: profiled GEMM
    gemm_tc<<<dim3(D / GBN, NTOK / GBM), NTHR, GEMM_SMEM>>>(h0, WqT, bq, q, NTOK, D, D, 0, 0);

    transpose_kernel<<<dim3(D / 32, D / 32), tb>>>(Wv, WvT, D, D);
    gemm_tc<<<dim3(D / GBN, NTOK / GBM), NTHR, GEMM_SMEM>>>(h0, WkT, bk, k, NTOK, D, D, 0, 0);
    gemm_tc<<<dim3(D / GBN, NTOK / GBM), NTHR, GEMM_SMEM>>>(h0, WvT, bv, v, NTOK, D, D, 0, 0);

    // remaining weight transposes (before their consumers)
    transpose_kernel<<<dim3(D / 32,     D / 32),   tb>>>(Wo, WoT, D,   D);
    transpose_kernel<<<dim3(DFF / 32,   D / 32),   tb>>>(W1, W1T, D,   DFF);
    transpose_kernel<<<dim3(D / 32,     DFF / 32), tb>>>(W2, W2T, DFF, D);
    transpose_kernel<<<dim3(VOCAB / 32, D / 32),   tb>>>(Wh, WhT, D,   VOCAB);

    // fused local-causal attention
    attn_kernel<<<NTOK, 128>>>(q, k, v, att);

    // output projection
    gemm_tc<<<dim3(D / GBN, NTOK / GBM), NTHR, GEMM_SMEM>>>(att, WoT, bo, o, NTOK, D, D, 0, 0);

    // residual + LN1
    add_ln_kernel<<<NTOK, 128>>>(h0, o, ln1g, ln1b, h1);

    // FFN (mid output tf32-rounded: consumed by FFN2 GEMM)
    gemm_tc<<<dim3(DFF / GBN, NTOK / GBM), NTHR, GEMM_SMEM>>>(h1, W1T, b1, mid, NTOK, DFF, D, 1, 1);
    gemm_tc<<<dim3(D / GBN, NTOK / GBM), NTHR, GEMM_SMEM>>>(mid, W2T, b2, f, NTOK, D, DFF, 0, 0);

    // residual + LN2
    add_ln_kernel<<<NTOK, 128>>>(h1, f, ln2g, ln2b, h2);

    // vocab head -> d_out
    gemm_tc<<<dim3(VOCAB / GBN, NTOK / GBM), NTHR, GEMM_SMEM>>>(h2, WhT, bh, out, NTOK, VOCAB, D, 0, 0);
}

// round 9
// speedup vs baseline: 1.5260x; 1.5088x over previous
#include <cuda_runtime.h>
#include <cuda_fp16.h>
#include <math.h>
#include <cstdint>

// ---------------------------------------------------------------------------
// Problem constants
// ---------------------------------------------------------------------------
#define B 8
#define SEQ 1024
#define WIN 9
#define D 512
#define DFF 1024
#define VOCAB 16384
#define NTOK (B * SEQ)   // 8192
#define EPS 1e-5f

// ---------------------------------------------------------------------------
// Scratch buffers (device globals: no allocation allowed)
// ---------------------------------------------------------------------------
__device__ float  g_h0  [NTOK * D];        // embed+pos, fp32 (residual)
__device__ __half g_h0h [NTOK * D];        // fp16 copy (QKV GEMM input)
__device__ float  g_qkv [NTOK * 3 * D];    // fused QKV output
__device__ __half g_atth[NTOK * D];        // attention out (O-proj input)
__device__ float  g_o   [NTOK * D];
__device__ float  g_h1  [NTOK * D];
__device__ __half g_h1h [NTOK * D];
__device__ __half g_midh[NTOK * DFF];
__device__ float  g_f   [NTOK * D];
__device__ __half g_h2h [NTOK * D];
// transposed fp16 weights ([N,K] K-major)
__device__ __half g_Wqkv[3 * D * D];
__device__ __half g_WoT [D * D];
__device__ __half g_W1T [DFF * D];
__device__ __half g_W2T [D * DFF];
__device__ __half g_WhT [VOCAB * D];
__device__ float  g_bqkv[3 * D];

// ---------------------------------------------------------------------------
// helpers (plain compute_103-legal PTX)
// ---------------------------------------------------------------------------
__device__ __forceinline__ uint32_t smem_to_u32(const void* p) {
    uint32_t a;
    asm("{ .reg .u64 t; cvta.to.shared.u64 t, %1; cvt.u32.u64 %0, t; }" : "=r"(a) : "l"(p));
    return a;
}
__device__ __forceinline__ void cp_async16(uint32_t saddr, const void* gptr) {
    asm volatile("cp.async.cg.shared.global [%0], [%1], 16;" :: "r"(saddr), "l"(gptr));
}
#define CP_COMMIT()  asm volatile("cp.async.commit_group;" ::: "memory")
#define CP_WAIT(n)   asm volatile("cp.async.wait_group %0;" :: "n"(n) : "memory")

__device__ __forceinline__ void ldsm_x4(uint32_t* d, uint32_t addr) {
    asm volatile("ldmatrix.sync.aligned.m8n8.x4.shared.b16 {%0,%1,%2,%3}, [%4];"
        : "=r"(d[0]), "=r"(d[1]), "=r"(d[2]), "=r"(d[3]) : "r"(addr));
}
__device__ __forceinline__ void mma_f16(float* d, const uint32_t* a, const uint32_t* b) {
    asm volatile(
        "mma.sync.aligned.m16n8k16.row.col.f32.f16.f16.f32 "
        "{%0,%1,%2,%3}, {%4,%5,%6,%7}, {%8,%9}, {%0,%1,%2,%3};"
        : "+f"(d[0]), "+f"(d[1]), "+f"(d[2]), "+f"(d[3])
        : "r"(a[0]), "r"(a[1]), "r"(a[2]), "r"(a[3]),
          "r"(b[0]), "r"(b[1]));
}

// ---------------------------------------------------------------------------
// Kernel: fp32->fp16 weight transpose   in[R][Cn] -> out[Cn][R]
// ---------------------------------------------------------------------------
__global__ void transpose_h(const float* __restrict__ in, __half* __restrict__ out,
                            int R, int Cn) {
    __shared__ float t[32][33];
    int bx = blockIdx.x * 32, by = blockIdx.y * 32;
    int x = bx + threadIdx.x;
    int y = by + threadIdx.y;
#pragma unroll
    for (int i = 0; i < 32; i += 8)
        t[threadIdx.y + i][threadIdx.x] = in[(size_t)(y + i) * Cn + x];
    __syncthreads();
    x = by + threadIdx.x;
    y = bx + threadIdx.y;
#pragma unroll
    for (int i = 0; i < 32; i += 8)
        out[(size_t)(y + i) * R + x] = __float2half_rn(t[threadIdx.x][threadIdx.y + i]);
}

// batched QKV transpose: z selects Wq/Wk/Wv (each [D][D]) -> Wqkv rows z*D..
__global__ void qkv_transpose(const float* __restrict__ Wq,
                              const float* __restrict__ Wk,
                              const float* __restrict__ Wv,
                              __half* __restrict__ out) {
    __shared__ float t[32][33];
    const float* in = (blockIdx.z == 0) ? Wq : (blockIdx.z == 1) ? Wk : Wv;
    __half* o = out + (size_t)blockIdx.z * D * D;
    int bx = blockIdx.x * 32, by = blockIdx.y * 32;
    int x = bx + threadIdx.x;
    int y = by + threadIdx.y;
#pragma unroll
    for (int i = 0; i < 32; i += 8)
        t[threadIdx.y + i][threadIdx.x] = in[(size_t)(y + i) * D + x];
    __syncthreads();
    x = by + threadIdx.x;
    y = bx + threadIdx.y;
#pragma unroll
    for (int i = 0; i < 32; i += 8)
        o[(size_t)(y + i) * D + x] = __float2half_rn(t[threadIdx.x][threadIdx.y + i]);
}

// ---------------------------------------------------------------------------
// Kernel: fp16 mma.sync GEMM  C[M,N] = A[M,K] @ Bt[N,K]^T + bias (+ReLU)
// CTA tile 256x128, BK=64 halves (128B rows), 512 threads (16 warps 4x4),
// warp tile 64x32, 4-stage cp.async pipeline, XOR swizzle, ldmatrix.x4.
// Output: Cf (fp32) or Ch (fp16) — exactly one non-null.
// ---------------------------------------------------------------------------
#define GBM 256
#define GBN 128
#define STAGES 4
#define NTHR 512
#define STAGE_AB (GBM * 128)   // bytes per A stage (256 rows x 128B)
#define STAGE_BB (GBN * 128)   // bytes per B stage

__global__ __launch_bounds__(NTHR, 1) void gemm_tc(
    const __half* __restrict__ A, const __half* __restrict__ Bt,
    const float* __restrict__ bias, float* __restrict__ Cf, __half* __restrict__ Ch,
    int M, int N, int K, int relu)
{
    extern __shared__ uint32_t smem[];
    const uint32_t sA_u32 = smem_to_u32(smem);
    const uint32_t sB_u32 = sA_u32 + STAGES * STAGE_AB;

    const int tid  = threadIdx.x;
    const int lane = tid & 31;
    const int wid  = tid >> 5;
    const int wm   = wid >> 2;           // 0..3  (M warps, 64 rows each)
    const int wn   = wid & 3;            // 0..3  (N warps, 32 cols each)
    const int bm   = blockIdx.y * GBM;
    const int bn   = blockIdx.x * GBN;
    const int nk   = K >> 6;             // 64 halves per chunk

    // cp.async per-thread coordinates (A: 4 x 16B, B: 2 x 16B per chunk)
    int ar[4], ac[4]; uint32_t aso[4];
#pragma unroll
    for (int t = 0; t < 4; t++) {
        int idx = t * NTHR + tid;        // 0..2047 = 256 rows x 8 groups
        ar[t] = idx >> 3; ac[t] = idx & 7;
        aso[t] = (uint32_t)(ar[t] * 128 + ((ac[t] ^ (ar[t] & 7)) << 4));
    }
    int br[2], bc[2]; uint32_t bso[2];
#pragma unroll
    for (int t = 0; t < 2; t++) {
        int idx = t * NTHR + tid;        // 0..1023 = 128 rows x 8 groups
        br[t] = idx >> 3; bc[t] = idx & 7;
        bso[t] = (uint32_t)(br[t] * 128 + ((bc[t] ^ (br[t] & 7)) << 4));
    }

    // ldmatrix per-thread constants (same byte geometry as tf32 version)
    uint32_t aRowB[4], aR7[4];
#pragma unroll
    for (int mf = 0; mf < 4; mf++) {
        int r = wm * 64 + mf * 16 + (lane & 15);
        aRowB[mf] = (uint32_t)r * 128u;
        aR7[mf]   = (uint32_t)(r & 7);
    }
    const uint32_t gselA = (lane >> 4) & 1;
    uint32_t bRowB[2], bR7[2];
#pragma unroll
    for (int np = 0; np < 2; np++) {
        int r = wn * 32 + np * 16 + (lane & 7) + ((lane >> 4) << 3);
        bRowB[np] = (uint32_t)r * 128u;
        bR7[np]   = (uint32_t)(r & 7);
    }
    const uint32_t gselB = (lane >> 3) & 1;

    float acc[4][4][4];
#pragma unroll
    for (int i = 0; i < 4; i++)
#pragma unroll
        for (int j = 0; j < 4; j++)
#pragma unroll
            for (int l = 0; l < 4; l++) acc[i][j][l] = 0.0f;

#define LOAD_STAGE(chunk, stage) do { \
    const int _kc = (chunk) << 6; \
    const uint32_t _sa = sA_u32 + (uint32_t)(stage) * STAGE_AB; \
    const uint32_t _sb = sB_u32 + (uint32_t)(stage) * STAGE_BB; \
    _Pragma("unroll") \
    for (int _t = 0; _t < 4; _t++) \
        cp_async16(_sa + aso[_t], A + (size_t)(bm + ar[_t]) * K + _kc + ac[_t] * 8); \
    _Pragma("unroll") \
    for (int _t = 0; _t < 2; _t++) \
        cp_async16(_sb + bso[_t], Bt + (size_t)(bn + br[_t]) * K + _kc + bc[_t] * 8); \
    CP_COMMIT(); \
} while (0)

    // prologue (nk >= 8 at every call site)
    LOAD_STAGE(0, 0);
    LOAD_STAGE(1, 1);
    LOAD_STAGE(2, 2);

    for (int chunk = 0; chunk < nk; chunk++) {
        CP_WAIT(STAGES - 2);
        __syncthreads();

        if (chunk + STAGES - 1 < nk) {
            LOAD_STAGE(chunk + STAGES - 1, (chunk + STAGES - 1) & (STAGES - 1));
        } else {
            CP_COMMIT();
        }

        const uint32_t saBase = sA_u32 + (uint32_t)(chunk & (STAGES - 1)) * STAGE_AB;
        const uint32_t sbBase = sB_u32 + (uint32_t)(chunk & (STAGES - 1)) * STAGE_BB;

#pragma unroll
        for (int ks = 0; ks < 4; ks++) {          // 4 x K=16 per 64-chunk
            const uint32_t gA = 2 * ks + gselA;
            const uint32_t gB = 2 * ks + gselB;
            uint32_t af[4][4];
#pragma unroll
            for (int mf = 0; mf < 4; mf++)
                ldsm_x4(af[mf], saBase + aRowB[mf] + ((gA ^ aR7[mf]) << 4));
            uint32_t bq[2][4];
#pragma unroll
            for (int np = 0; np < 2; np++)
                ldsm_x4(bq[np], sbBase + bRowB[np] + ((gB ^ bR7[np]) << 4));
#pragma unroll
            for (int mf = 0; mf < 4; mf++)
#pragma unroll
                for (int nf = 0; nf < 4; nf++)
                    mma_f16(acc[mf][nf], af[mf], &bq[nf >> 1][(nf & 1) * 2]);
        }
    }

    // ---- epilogue ----
#pragma unroll
    for (int mf = 0; mf < 4; mf++) {
        int row0 = bm + wm * 64 + mf * 16 + (lane >> 2);
#pragma unroll
        for (int nf = 0; nf < 4; nf++) {
            int col = bn + wn * 32 + nf * 8 + (lane & 3) * 2;
            float bx = bias[col], by = bias[col + 1];
            float2 v0, v1;
            v0.x = acc[mf][nf][0] + bx; v0.y = acc[mf][nf][1] + by;
            v1.x = acc[mf][nf][2] + bx; v1.y = acc[mf][nf][3] + by;
            if (relu) {
                v0.x = fmaxf(v0.x, 0.0f); v0.y = fmaxf(v0.y, 0.0f);
                v1.x = fmaxf(v1.x, 0.0f); v1.y = fmaxf(v1.y, 0.0f);
            }
            if (Cf) {
                *(float2*)(Cf + (size_t)row0 * N + col)       = v0;
                *(float2*)(Cf + (size_t)(row0 + 8) * N + col) = v1;
            } else {
                *(__half2*)(Ch + (size_t)row0 * N + col)       = __floats2half2_rn(v0.x, v0.y);
                *(__half2*)(Ch + (size_t)(row0 + 8) * N + col) = __floats2half2_rn(v1.x, v1.y);
            }
        }
    }
}

// ---------------------------------------------------------------------------
// Kernel: embedding + 2D pos (fp32 + fp16 outputs) and QKV bias concat
// grid = NTOK + 12; blocks >= NTOK handle the 1536-entry bias concat
// ---------------------------------------------------------------------------
__global__ void embed_kernel(const int* __restrict__ x,
                             const float* __restrict__ tab,
                             const float* __restrict__ rowe,
                             const float* __restrict__ cole,
                             const float* __restrict__ bq,
                             const float* __restrict__ bk,
                             const float* __restrict__ bv,
                             float* __restrict__ h,
                             __half* __restrict__ hh,
                             float* __restrict__ bqkv) {
    int qi = blockIdx.x;
    if (qi >= NTOK) {
        int i = (qi - NTOK) * 128 + threadIdx.x;
        if (i < 3 * D)
            bqkv[i] = (i < D) ? bq[i] : (i < 2 * D) ? bk[i - D] : bv[i - 2 * D];
        return;
    }
    int s  = qi & (SEQ - 1);
    int r  = s >> 5, c = s & 31;
    int tok = x[qi];
    int d = threadIdx.x * 4;

    float4 e = *(const float4*)&tab[(size_t)tok * D + d];
    float4 p;
    if (d < D / 2) p = *(const float4*)&rowe[r * (D / 2) + d];
    else           p = *(const float4*)&cole[c * (D / 2) + (d - D / 2)];
    e.x += p.x; e.y += p.y; e.z += p.z; e.w += p.w;
    *(float4*)&h[(size_t)qi * D + d] = e;
    *(__half2*)&hh[(size_t)qi * D + d]     = __floats2half2_rn(e.x, e.y);
    *(__half2*)&hh[(size_t)qi * D + d + 2] = __floats2half2_rn(e.z, e.w);
}

// ---------------------------------------------------------------------------
// Kernel: fused local-causal attention over fused QKV buffer (stride 3D)
// output fp16 (only consumed by O-proj GEMM)
// ---------------------------------------------------------------------------
__global__ void attn_kernel(const float* __restrict__ QKV,
                            __half* __restrict__ O) {
    int qi = blockIdx.x;
    int b = qi >> 10, s = qi & (SEQ - 1);
    int r = s >> 5, c = s & 31;
    int r0 = (r - WIN < 0) ? 0 : r - WIN;
    int c0 = (c - WIN < 0) ? 0 : c - WIN;
    int c1 = (c + WIN > 31) ? 31 : c + WIN;
    int wcols = c1 - c0 + 1;
    int nfull = r - r0;
    int nk = nfull * wcols + (c - c0 + 1);

    __shared__ float qv[D];
    __shared__ float sc[256];
    __shared__ int   kid[256];
    __shared__ float red[4];

    int tid = threadIdx.x;
    int lane = tid & 31, wid = tid >> 5;

    *(float4*)&qv[tid * 4] = *(const float4*)&QKV[(size_t)qi * (3 * D) + tid * 4];
    __syncthreads();

    const float scale = 0.044194173824159216f;
    const float* kbase = QKV + (size_t)b * SEQ * (3 * D) + D;

    for (int j = wid; j < nk; j += 4) {
        int row, col;
        if (j < nfull * wcols) { row = r0 + j / wcols; col = c0 + j % wcols; }
        else                   { row = r;             col = c0 + (j - nfull * wcols); }
        int kk = row * 32 + col;
        const float* krow = kbase + (size_t)kk * (3 * D);
        float sum = 0.0f;
#pragma unroll
        for (int t = 0; t < D / 32; t++)
            sum = fmaf(qv[lane + 32 * t], krow[lane + 32 * t], sum);
#pragma unroll
        for (int off = 16; off; off >>= 1)
            sum += __shfl_xor_sync(0xffffffffu, sum, off);
        if (lane == 0) { sc[j] = sum * scale; kid[j] = kk; }
    }
    __syncthreads();

    float m = -1e30f;
    for (int j = tid; j < nk; j += 128) m = fmaxf(m, sc[j]);
#pragma unroll
    for (int off = 16; off; off >>= 1)
        m = fmaxf(m, __shfl_xor_sync(0xffffffffu, m, off));
    if (lane == 0) red[wid] = m;
    __syncthreads();
    m = fmaxf(fmaxf(red[0], red[1]), fmaxf(red[2], red[3]));

    float ssum = 0.0f;
    for (int j = tid; j < nk; j += 128) {
        float e = __expf(sc[j] - m);
        sc[j] = e;
        ssum += e;
    }
    __syncthreads();
#pragma unroll
    for (int off = 16; off; off >>= 1)
        ssum += __shfl_xor_sync(0xffffffffu, ssum, off);
    if (lane == 0) red[wid] = ssum;
    __syncthreads();
    float inv = 1.0f / (red[0] + red[1] + red[2] + red[3]);

    const float* vbase = QKV + (size_t)b * SEQ * (3 * D) + 2 * D;
    int d = tid * 4;
    float4 acc = make_float4(0.f, 0.f, 0.f, 0.f);
    for (int j = 0; j < nk; j++) {
        float w = sc[j] * inv;
        float4 v = *(const float4*)&vbase[(size_t)kid[j] * (3 * D) + d];
        acc.x = fmaf(w, v.x, acc.x);
        acc.y = fmaf(w, v.y, acc.y);
        acc.z = fmaf(w, v.z, acc.z);
        acc.w = fmaf(w, v.w, acc.w);
    }
    *(__half2*)&O[(size_t)qi * D + d]     = __floats2half2_rn(acc.x, acc.y);
    *(__half2*)&O[(size_t)qi * D + d + 2] = __floats2half2_rn(acc.z, acc.w);
}

// ---------------------------------------------------------------------------
// Kernel: LayerNorm(X + Y) * g + b  ->  fp32 out (optional) + fp16 out (optional)
// ---------------------------------------------------------------------------
__global__ void add_ln_kernel(const float* __restrict__ X,
                              const float* __restrict__ Y,
                              const float* __restrict__ g,
                              const float* __restrict__ beta,
                              float* __restrict__ outf,
                              __half* __restrict__ outh) {
    int row = blockIdx.x;
    int tid = threadIdx.x;
    int lane = tid & 31, wid = tid >> 5;
    __shared__ float reds[4], redq[4];

    int d = tid * 4;
    float4 xv = *(const float4*)&X[(size_t)row * D + d];
    float4 yv = *(const float4*)&Y[(size_t)row * D + d];
    xv.x += yv.x; xv.y += yv.y; xv.z += yv.z; xv.w += yv.w;

    float s  = xv.x + xv.y + xv.z + xv.w;
    float sq = xv.x * xv.x + xv.y * xv.y + xv.z * xv.z + xv.w * xv.w;
#pragma unroll
    for (int off = 16; off; off >>= 1) {
        s  += __shfl_xor_sync(0xffffffffu, s,  off);
        sq += __shfl_xor_sync(0xffffffffu, sq, off);
    }
    if (lane == 0) { reds[wid] = s; redq[wid] = sq; }
    __syncthreads();
    s  = reds[0] + reds[1] + reds[2] + reds[3];
    sq = redq[0] + redq[1] + redq[2] + redq[3];

    float mu  = s * (1.0f / D);
    float var = sq * (1.0f / D) - mu * mu;
    float rstd = rsqrtf(var + EPS);

    float4 gv = *(const float4*)&g[d];
    float4 bv = *(const float4*)&beta[d];
    float4 o;
    o.x = (xv.x - mu) * rstd * gv.x + bv.x;
    o.y = (xv.y - mu) * rstd * gv.y + bv.y;
    o.z = (xv.z - mu) * rstd * gv.z + bv.z;
    o.w = (xv.w - mu) * rstd * gv.w + bv.w;
    if (outf) *(float4*)&outf[(size_t)row * D + d] = o;
    if (outh) {
        *(__half2*)&outh[(size_t)row * D + d]     = __floats2half2_rn(o.x, o.y);
        *(__half2*)&outh[(size_t)row * D + d + 2] = __floats2half2_rn(o.z, o.w);
    }
}

// ---------------------------------------------------------------------------
// Launch   (ncu -s5 -c1 captures launch index 3 => fused QKV GEMM there)
// ---------------------------------------------------------------------------
extern "C" void kernel_launch(void* const* d_in, const int* in_sizes, int n_in,
                              void* d_out, int out_size) {
    const int*   x     = (const int*)  d_in[0];
    const float* tab   = (const float*)d_in[1];
    const float* rowe  = (const float*)d_in[2];
    const float* cole  = (const float*)d_in[3];
    const float* Wq    = (const float*)d_in[4];
    const float* bq    = (const float*)d_in[5];
    const float* Wk    = (const float*)d_in[6];
    const float* bk    = (const float*)d_in[7];
    const float* Wv    = (const float*)d_in[8];
    const float* bv    = (const float*)d_in[9];
    const float* Wo    = (const float*)d_in[10];
    const float* bo    = (const float*)d_in[11];
    const float* ln1g  = (const float*)d_in[12];
    const float* ln1b  = (const float*)d_in[13];
    const float* W1    = (const float*)d_in[14];
    const float* b1    = (const float*)d_in[15];
    const float* W2    = (const float*)d_in[16];
    const float* b2    = (const float*)d_in[17];
    const float* ln2g  = (const float*)d_in[18];
    const float* ln2b  = (const float*)d_in[19];
    const float* Wh    = (const float*)d_in[20];
    const float* bh    = (const float*)d_in[21];
    float* out = (float*)d_out;

    float *h0, *qkv, *o, *h1, *f, *bqkv;
    __half *h0h, *atth, *h1h, *midh, *h2h;
    __half *Wqkv, *WoT, *W1T, *W2T, *WhT;
    cudaGetSymbolAddress((void**)&h0,   g_h0);
    cudaGetSymbolAddress((void**)&h0h,  g_h0h);
    cudaGetSymbolAddress((void**)&qkv,  g_qkv);
    cudaGetSymbolAddress((void**)&atth, g_atth);
    cudaGetSymbolAddress((void**)&o,    g_o);
    cudaGetSymbolAddress((void**)&h1,   g_h1);
    cudaGetSymbolAddress((void**)&h1h,  g_h1h);
    cudaGetSymbolAddress((void**)&midh, g_midh);
    cudaGetSymbolAddress((void**)&f,    g_f);
    cudaGetSymbolAddress((void**)&h2h,  g_h2h);
    cudaGetSymbolAddress((void**)&Wqkv, g_Wqkv);
    cudaGetSymbolAddress((void**)&WoT,  g_WoT);
    cudaGetSymbolAddress((void**)&W1T,  g_W1T);
    cudaGetSymbolAddress((void**)&W2T,  g_W2T);
    cudaGetSymbolAddress((void**)&WhT,  g_WhT);
    cudaGetSymbolAddress((void**)&bqkv, g_bqkv);

    const int GEMM_SMEM = STAGES * (STAGE_AB + STAGE_BB);  // 196608 bytes
    static int attr_set = 0;
    if (!attr_set) {
        cudaFuncSetAttribute(gemm_tc, cudaFuncAttributeMaxDynamicSharedMemorySize, GEMM_SMEM);
        attr_set = 1;
    }

    dim3 tb(32, 8);

    // 0: embed (+ bias concat in tail blocks)
    embed_kernel<<<NTOK + 12, 128>>>(x, tab, rowe, cole, bq, bk, bv, h0, h0h, bqkv);
    // 1: fused QKV weight transpose
    qkv_transpose<<<dim3(16, 16, 3), tb>>>(Wq, Wk, Wv, Wqkv);
    // 2: Wo transpose
    transpose_h<<<dim3(16, 16), tb>>>(Wo, WoT, D, D);
    // 3: fused QKV GEMM (profiled)
    gemm_tc<<<dim3(3 * D / GBN, NTOK / GBM), NTHR, GEMM_SMEM>>>(
        h0h, Wqkv, bqkv, qkv, nullptr, NTOK, 3 * D, D, 0);

    // remaining weight transposes
    transpose_h<<<dim3(DFF / 32,   D / 32),   tb>>>(W1, W1T, D,   DFF);
    transpose_h<<<dim3(D / 32,     DFF / 32), tb>>>(W2, W2T, DFF, D);
    transpose_h<<<dim3(VOCAB / 32, D / 32),   tb>>>(Wh, WhT, D,   VOCAB);

    // attention
    attn_kernel<<<NTOK, 128>>>(qkv, atth);

    // O projection
    gemm_tc<<<dim3(D / GBN, NTOK / GBM), NTHR, GEMM_SMEM>>>(
        atth, WoT, bo, o, nullptr, NTOK, D, D, 0);

    // residual + LN1 (fp32 for residual, fp16 for FFN1)
    add_ln_kernel<<<NTOK, 128>>>(h0, o, ln1g, ln1b, h1, h1h);

    // FFN
    gemm_tc<<<dim3(DFF / GBN, NTOK / GBM), NTHR, GEMM_SMEM>>>(
        h1h, W1T, b1, nullptr, midh, NTOK, DFF, D, 1);
    gemm_tc<<<dim3(D / GBN, NTOK / GBM), NTHR, GEMM_SMEM>>>(
        midh, W2T, b2, f, nullptr, NTOK, D, DFF, 0);

    // residual + LN2 (fp16 only; only the head consumes it)
    add_ln_kernel<<<NTOK, 128>>>(h1, f, ln2g, ln2b, nullptr, h2h);

    // vocab head -> d_out
    gemm_tc<<<dim3(VOCAB / GBN, NTOK / GBM), NTHR, GEMM_SMEM>>>(
        h2h, WhT, bh, out, nullptr, NTOK, VOCAB, D, 0);
}

// round 10
// speedup vs baseline: 1.6201x; 1.0617x over previous
#include <cuda_runtime.h>
#include <cuda_fp16.h>
#include <math.h>
#include <cstdint>

// ---------------------------------------------------------------------------
// Problem constants
// ---------------------------------------------------------------------------
#define B 8
#define SEQ 1024
#define WIN 9
#define D 512
#define DFF 1024
#define VOCAB 16384
#define NTOK (B * SEQ)   // 8192
#define EPS 1e-5f

// ---------------------------------------------------------------------------
// Scratch buffers (device globals: no allocation allowed)
// ---------------------------------------------------------------------------
__device__ float  g_h0  [NTOK * D];        // embed+pos, fp32 (residual)
__device__ __half g_h0h [NTOK * D];        // fp16 copy (QKV GEMM input)
__device__ float  g_qkv [NTOK * 3 * D];    // fused QKV output
__device__ __half g_atth[NTOK * D];        // attention out (O-proj input)
__device__ float  g_o   [NTOK * D];
__device__ float  g_h1  [NTOK * D];
__device__ __half g_h1h [NTOK * D];
__device__ __half g_midh[NTOK * DFF];
__device__ float  g_f   [NTOK * D];
__device__ __half g_h2h [NTOK * D];
// transposed fp16 weights ([N,K] K-major)
__device__ __half g_Wqkv[3 * D * D];
__device__ __half g_WoT [D * D];
__device__ __half g_W1T [DFF * D];
__device__ __half g_W2T [D * DFF];
__device__ __half g_WhT [VOCAB * D];
__device__ float  g_bqkv[3 * D];

// ---------------------------------------------------------------------------
// helpers (plain compute_103-legal PTX)
// ---------------------------------------------------------------------------
__device__ __forceinline__ uint32_t smem_to_u32(const void* p) {
    uint32_t a;
    asm("{ .reg .u64 t; cvta.to.shared.u64 t, %1; cvt.u32.u64 %0, t; }" : "=r"(a) : "l"(p));
    return a;
}
__device__ __forceinline__ void cp_async16(uint32_t saddr, const void* gptr) {
    asm volatile("cp.async.cg.shared.global [%0], [%1], 16;" :: "r"(saddr), "l"(gptr));
}
#define CP_COMMIT()  asm volatile("cp.async.commit_group;" ::: "memory")
#define CP_WAIT(n)   asm volatile("cp.async.wait_group %0;" :: "n"(n) : "memory")

__device__ __forceinline__ void ldsm_x4(uint32_t* d, uint32_t addr) {
    asm volatile("ldmatrix.sync.aligned.m8n8.x4.shared.b16 {%0,%1,%2,%3}, [%4];"
        : "=r"(d[0]), "=r"(d[1]), "=r"(d[2]), "=r"(d[3]) : "r"(addr));
}
__device__ __forceinline__ void mma_f16(float* d, const uint32_t* a, const uint32_t* b) {
    asm volatile(
        "mma.sync.aligned.m16n8k16.row.col.f32.f16.f16.f32 "
        "{%0,%1,%2,%3}, {%4,%5,%6,%7}, {%8,%9}, {%0,%1,%2,%3};"
        : "+f"(d[0]), "+f"(d[1]), "+f"(d[2]), "+f"(d[3])
        : "r"(a[0]), "r"(a[1]), "r"(a[2]), "r"(a[3]),
          "r"(b[0]), "r"(b[1]));
}

// ---------------------------------------------------------------------------
// Kernel: fp32->fp16 weight transpose   in[R][Cn] -> out[Cn][R]
// ---------------------------------------------------------------------------
__global__ void transpose_h(const float* __restrict__ in, __half* __restrict__ out,
                            int R, int Cn) {
    __shared__ float t[32][33];
    int bx = blockIdx.x * 32, by = blockIdx.y * 32;
    int x = bx + threadIdx.x;
    int y = by + threadIdx.y;
#pragma unroll
    for (int i = 0; i < 32; i += 8)
        t[threadIdx.y + i][threadIdx.x] = in[(size_t)(y + i) * Cn + x];
    __syncthreads();
    x = by + threadIdx.x;
    y = bx + threadIdx.y;
#pragma unroll
    for (int i = 0; i < 32; i += 8)
        out[(size_t)(y + i) * R + x] = __float2half_rn(t[threadIdx.x][threadIdx.y + i]);
}

// batched QKV transpose: z selects Wq/Wk/Wv (each [D][D]) -> Wqkv rows z*D..
__global__ void qkv_transpose(const float* __restrict__ Wq,
                              const float* __restrict__ Wk,
                              const float* __restrict__ Wv,
                              __half* __restrict__ out) {
    __shared__ float t[32][33];
    const float* in = (blockIdx.z == 0) ? Wq : (blockIdx.z == 1) ? Wk : Wv;
    __half* o = out + (size_t)blockIdx.z * D * D;
    int bx = blockIdx.x * 32, by = blockIdx.y * 32;
    int x = bx + threadIdx.x;
    int y = by + threadIdx.y;
#pragma unroll
    for (int i = 0; i < 32; i += 8)
        t[threadIdx.y + i][threadIdx.x] = in[(size_t)(y + i) * D + x];
    __syncthreads();
    x = by + threadIdx.x;
    y = bx + threadIdx.y;
#pragma unroll
    for (int i = 0; i < 32; i += 8)
        o[(size_t)(y + i) * D + x] = __float2half_rn(t[threadIdx.x][threadIdx.y + i]);
}

// ---------------------------------------------------------------------------
// Kernel: fp16 mma.sync GEMM  C[M,N] = A[M,K] @ Bt[N,K]^T + bias (+ReLU)
// CTA tile 128x128, BK=64 halves, 256 threads (8 warps 2x4), warp tile 64x32,
// 3-stage cp.async pipeline (96KB smem -> 2 CTAs/SM), XOR swizzle, ldmatrix.
// Output: Cf (fp32) or Ch (fp16) — exactly one non-null.
// ---------------------------------------------------------------------------
#define GBM 128
#define GBN 128
#define STAGES 3
#define NTHR 256
#define STAGE_AB (GBM * 128)   // bytes per A stage (128 rows x 128B)
#define STAGE_BB (GBN * 128)   // bytes per B stage

__global__ __launch_bounds__(NTHR, 2) void gemm_tc(
    const __half* __restrict__ A, const __half* __restrict__ Bt,
    const float* __restrict__ bias, float* __restrict__ Cf, __half* __restrict__ Ch,
    int M, int N, int K, int relu)
{
    extern __shared__ uint32_t smem[];
    const uint32_t sA_u32 = smem_to_u32(smem);
    const uint32_t sB_u32 = sA_u32 + STAGES * STAGE_AB;

    const int tid  = threadIdx.x;
    const int lane = tid & 31;
    const int wid  = tid >> 5;
    const int wm   = wid >> 2;           // 0..1  (M warps, 64 rows each)
    const int wn   = wid & 3;            // 0..3  (N warps, 32 cols each)
    const int bm   = blockIdx.y * GBM;
    const int bn   = blockIdx.x * GBN;
    const int nk   = K >> 6;             // 64 halves per chunk

    // cp.async per-thread coordinates (A: 4 x 16B, B: 4 x 16B per chunk)
    int ar[4], ac[4]; uint32_t aso[4];
#pragma unroll
    for (int t = 0; t < 4; t++) {
        int idx = t * NTHR + tid;        // 0..1023 = 128 rows x 8 groups
        ar[t] = idx >> 3; ac[t] = idx & 7;
        aso[t] = (uint32_t)(ar[t] * 128 + ((ac[t] ^ (ar[t] & 7)) << 4));
    }

    // ldmatrix per-thread constants
    uint32_t aRowB[4], aR7[4];
#pragma unroll
    for (int mf = 0; mf < 4; mf++) {
        int r = wm * 64 + mf * 16 + (lane & 15);
        aRowB[mf] = (uint32_t)r * 128u;
        aR7[mf]   = (uint32_t)(r & 7);
    }
    const uint32_t gselA = (lane >> 4) & 1;
    uint32_t bRowB[2], bR7[2];
#pragma unroll
    for (int np = 0; np < 2; np++) {
        int r = wn * 32 + np * 16 + (lane & 7) + ((lane >> 4) << 3);
        bRowB[np] = (uint32_t)r * 128u;
        bR7[np]   = (uint32_t)(r & 7);
    }
    const uint32_t gselB = (lane >> 3) & 1;

    float acc[4][4][4];
#pragma unroll
    for (int i = 0; i < 4; i++)
#pragma unroll
        for (int j = 0; j < 4; j++)
#pragma unroll
            for (int l = 0; l < 4; l++) acc[i][j][l] = 0.0f;

#define LOAD_STAGE(chunk, stage) do { \
    const int _kc = (chunk) << 6; \
    const uint32_t _sa = sA_u32 + (uint32_t)(stage) * STAGE_AB; \
    const uint32_t _sb = sB_u32 + (uint32_t)(stage) * STAGE_BB; \
    _Pragma("unroll") \
    for (int _t = 0; _t < 4; _t++) \
        cp_async16(_sa + aso[_t], A + (size_t)(bm + ar[_t]) * K + _kc + ac[_t] * 8); \
    _Pragma("unroll") \
    for (int _t = 0; _t < 4; _t++) \
        cp_async16(_sb + aso[_t], Bt + (size_t)(bn + ar[_t]) * K + _kc + ac[_t] * 8); \
    CP_COMMIT(); \
} while (0)

    // prologue: stages 0..1   (nk >= 8 at every call site)
    LOAD_STAGE(0, 0);
    LOAD_STAGE(1, 1);

    int cur = 0, nxt = 2;   // stage holding 'chunk'; stage receiving 'chunk+2'
    for (int chunk = 0; chunk < nk; chunk++) {
        CP_WAIT(STAGES - 2);
        __syncthreads();

        if (chunk + 2 < nk) {
            LOAD_STAGE(chunk + 2, nxt);
        } else {
            CP_COMMIT();
        }

        const uint32_t saBase = sA_u32 + (uint32_t)cur * STAGE_AB;
        const uint32_t sbBase = sB_u32 + (uint32_t)cur * STAGE_BB;

#pragma unroll
        for (int ks = 0; ks < 4; ks++) {          // 4 x K=16 per 64-chunk
            const uint32_t gA = 2 * ks + gselA;
            const uint32_t gB = 2 * ks + gselB;
            uint32_t af[4][4];
#pragma unroll
            for (int mf = 0; mf < 4; mf++)
                ldsm_x4(af[mf], saBase + aRowB[mf] + ((gA ^ aR7[mf]) << 4));
            uint32_t bq[2][4];
#pragma unroll
            for (int np = 0; np < 2; np++)
                ldsm_x4(bq[np], sbBase + bRowB[np] + ((gB ^ bR7[np]) << 4));
#pragma unroll
            for (int mf = 0; mf < 4; mf++)
#pragma unroll
                for (int nf = 0; nf < 4; nf++)
                    mma_f16(acc[mf][nf], af[mf], &bq[nf >> 1][(nf & 1) * 2]);
        }
        cur = (cur == 2) ? 0 : cur + 1;
        nxt = (nxt == 2) ? 0 : nxt + 1;
    }

    // ---- epilogue ----
#pragma unroll
    for (int mf = 0; mf < 4; mf++) {
        int row0 = bm + wm * 64 + mf * 16 + (lane >> 2);
#pragma unroll
        for (int nf = 0; nf < 4; nf++) {
            int col = bn + wn * 32 + nf * 8 + (lane & 3) * 2;
            float bx = bias[col], by = bias[col + 1];
            float2 v0, v1;
            v0.x = acc[mf][nf][0] + bx; v0.y = acc[mf][nf][1] + by;
            v1.x = acc[mf][nf][2] + bx; v1.y = acc[mf][nf][3] + by;
            if (relu) {
                v0.x = fmaxf(v0.x, 0.0f); v0.y = fmaxf(v0.y, 0.0f);
                v1.x = fmaxf(v1.x, 0.0f); v1.y = fmaxf(v1.y, 0.0f);
            }
            if (Cf) {
                *(float2*)(Cf + (size_t)row0 * N + col)       = v0;
                *(float2*)(Cf + (size_t)(row0 + 8) * N + col) = v1;
            } else {
                *(__half2*)(Ch + (size_t)row0 * N + col)       = __floats2half2_rn(v0.x, v0.y);
                *(__half2*)(Ch + (size_t)(row0 + 8) * N + col) = __floats2half2_rn(v1.x, v1.y);
            }
        }
    }
}

// ---------------------------------------------------------------------------
// Kernel: embedding + 2D pos (fp32 + fp16 outputs) and QKV bias concat
// grid = NTOK + 12; blocks >= NTOK handle the 1536-entry bias concat
// ---------------------------------------------------------------------------
__global__ void embed_kernel(const int* __restrict__ x,
                             const float* __restrict__ tab,
                             const float* __restrict__ rowe,
                             const float* __restrict__ cole,
                             const float* __restrict__ bq,
                             const float* __restrict__ bk,
                             const float* __restrict__ bv,
                             float* __restrict__ h,
                             __half* __restrict__ hh,
                             float* __restrict__ bqkv) {
    int qi = blockIdx.x;
    if (qi >= NTOK) {
        int i = (qi - NTOK) * 128 + threadIdx.x;
        if (i < 3 * D)
            bqkv[i] = (i < D) ? bq[i] : (i < 2 * D) ? bk[i - D] : bv[i - 2 * D];
        return;
    }
    int s  = qi & (SEQ - 1);
    int r  = s >> 5, c = s & 31;
    int tok = x[qi];
    int d = threadIdx.x * 4;

    float4 e = *(const float4*)&tab[(size_t)tok * D + d];
    float4 p;
    if (d < D / 2) p = *(const float4*)&rowe[r * (D / 2) + d];
    else           p = *(const float4*)&cole[c * (D / 2) + (d - D / 2)];
    e.x += p.x; e.y += p.y; e.z += p.z; e.w += p.w;
    *(float4*)&h[(size_t)qi * D + d] = e;
    *(__half2*)&hh[(size_t)qi * D + d]     = __floats2half2_rn(e.x, e.y);
    *(__half2*)&hh[(size_t)qi * D + d + 2] = __floats2half2_rn(e.z, e.w);
}

// ---------------------------------------------------------------------------
// Kernel: fused local-causal attention over fused QKV buffer (stride 3D)
// output fp16 (only consumed by O-proj GEMM)
// ---------------------------------------------------------------------------
__global__ void attn_kernel(const float* __restrict__ QKV,
                            __half* __restrict__ O) {
    int qi = blockIdx.x;
    int b = qi >> 10, s = qi & (SEQ - 1);
    int r = s >> 5, c = s & 31;
    int r0 = (r - WIN < 0) ? 0 : r - WIN;
    int c0 = (c - WIN < 0) ? 0 : c - WIN;
    int c1 = (c + WIN > 31) ? 31 : c + WIN;
    int wcols = c1 - c0 + 1;
    int nfull = r - r0;
    int nk = nfull * wcols + (c - c0 + 1);

    __shared__ float qv[D];
    __shared__ float sc[256];
    __shared__ int   kid[256];
    __shared__ float red[4];

    int tid = threadIdx.x;
    int lane = tid & 31, wid = tid >> 5;

    *(float4*)&qv[tid * 4] = *(const float4*)&QKV[(size_t)qi * (3 * D) + tid * 4];
    __syncthreads();

    const float scale = 0.044194173824159216f;
    const float* kbase = QKV + (size_t)b * SEQ * (3 * D) + D;

    for (int j = wid; j < nk; j += 4) {
        int row, col;
        if (j < nfull * wcols) { row = r0 + j / wcols; col = c0 + j % wcols; }
        else                   { row = r;             col = c0 + (j - nfull * wcols); }
        int kk = row * 32 + col;
        const float* krow = kbase + (size_t)kk * (3 * D);
        float sum = 0.0f;
#pragma unroll
        for (int t = 0; t < D / 32; t++)
            sum = fmaf(qv[lane + 32 * t], krow[lane + 32 * t], sum);
#pragma unroll
        for (int off = 16; off; off >>= 1)
            sum += __shfl_xor_sync(0xffffffffu, sum, off);
        if (lane == 0) { sc[j] = sum * scale; kid[j] = kk; }
    }
    __syncthreads();

    float m = -1e30f;
    for (int j = tid; j < nk; j += 128) m = fmaxf(m, sc[j]);
#pragma unroll
    for (int off = 16; off; off >>= 1)
        m = fmaxf(m, __shfl_xor_sync(0xffffffffu, m, off));
    if (lane == 0) red[wid] = m;
    __syncthreads();
    m = fmaxf(fmaxf(red[0], red[1]), fmaxf(red[2], red[3]));

    float ssum = 0.0f;
    for (int j = tid; j < nk; j += 128) {
        float e = __expf(sc[j] - m);
        sc[j] = e;
        ssum += e;
    }
    __syncthreads();
#pragma unroll
    for (int off = 16; off; off >>= 1)
        ssum += __shfl_xor_sync(0xffffffffu, ssum, off);
    if (lane == 0) red[wid] = ssum;
    __syncthreads();
    float inv = 1.0f / (red[0] + red[1] + red[2] + red[3]);

    const float* vbase = QKV + (size_t)b * SEQ * (3 * D) + 2 * D;
    int d = tid * 4;
    float4 acc = make_float4(0.f, 0.f, 0.f, 0.f);
    for (int j = 0; j < nk; j++) {
        float w = sc[j] * inv;
        float4 v = *(const float4*)&vbase[(size_t)kid[j] * (3 * D) + d];
        acc.x = fmaf(w, v.x, acc.x);
        acc.y = fmaf(w, v.y, acc.y);
        acc.z = fmaf(w, v.z, acc.z);
        acc.w = fmaf(w, v.w, acc.w);
    }
    *(__half2*)&O[(size_t)qi * D + d]     = __floats2half2_rn(acc.x, acc.y);
    *(__half2*)&O[(size_t)qi * D + d + 2] = __floats2half2_rn(acc.z, acc.w);
}

// ---------------------------------------------------------------------------
// Kernel: LayerNorm(X + Y) * g + b  ->  fp32 out (optional) + fp16 out (optional)
// ---------------------------------------------------------------------------
__global__ void add_ln_kernel(const float* __restrict__ X,
                              const float* __restrict__ Y,
                              const float* __restrict__ g,
                              const float* __restrict__ beta,
                              float* __restrict__ outf,
                              __half* __restrict__ outh) {
    int row = blockIdx.x;
    int tid = threadIdx.x;
    int lane = tid & 31, wid = tid >> 5;
    __shared__ float reds[4], redq[4];

    int d = tid * 4;
    float4 xv = *(const float4*)&X[(size_t)row * D + d];
    float4 yv = *(const float4*)&Y[(size_t)row * D + d];
    xv.x += yv.x; xv.y += yv.y; xv.z += yv.z; xv.w += yv.w;

    float s  = xv.x + xv.y + xv.z + xv.w;
    float sq = xv.x * xv.x + xv.y * xv.y + xv.z * xv.z + xv.w * xv.w;
#pragma unroll
    for (int off = 16; off; off >>= 1) {
        s  += __shfl_xor_sync(0xffffffffu, s,  off);
        sq += __shfl_xor_sync(0xffffffffu, sq, off);
    }
    if (lane == 0) { reds[wid] = s; redq[wid] = sq; }
    __syncthreads();
    s  = reds[0] + reds[1] + reds[2] + reds[3];
    sq = redq[0] + redq[1] + redq[2] + redq[3];

    float mu  = s * (1.0f / D);
    float var = sq * (1.0f / D) - mu * mu;
    float rstd = rsqrtf(var + EPS);

    float4 gv = *(const float4*)&g[d];
    float4 bv = *(const float4*)&beta[d];
    float4 o;
    o.x = (xv.x - mu) * rstd * gv.x + bv.x;
    o.y = (xv.y - mu) * rstd * gv.y + bv.y;
    o.z = (xv.z - mu) * rstd * gv.z + bv.z;
    o.w = (xv.w - mu) * rstd * gv.w + bv.w;
    if (outf) *(float4*)&outf[(size_t)row * D + d] = o;
    if (outh) {
        *(__half2*)&outh[(size_t)row * D + d]     = __floats2half2_rn(o.x, o.y);
        *(__half2*)&outh[(size_t)row * D + d + 2] = __floats2half2_rn(o.z, o.w);
    }
}

// ---------------------------------------------------------------------------
// Launch   (ncu -s5 -c1 captures launch index 3 => fused QKV GEMM there)
// ---------------------------------------------------------------------------
extern "C" void kernel_launch(void* const* d_in, const int* in_sizes, int n_in,
                              void* d_out, int out_size) {
    const int*   x     = (const int*)  d_in[0];
    const float* tab   = (const float*)d_in[1];
    const float* rowe  = (const float*)d_in[2];
    const float* cole  = (const float*)d_in[3];
    const float* Wq    = (const float*)d_in[4];
    const float* bq    = (const float*)d_in[5];
    const float* Wk    = (const float*)d_in[6];
    const float* bk    = (const float*)d_in[7];
    const float* Wv    = (const float*)d_in[8];
    const float* bv    = (const float*)d_in[9];
    const float* Wo    = (const float*)d_in[10];
    const float* bo    = (const float*)d_in[11];
    const float* ln1g  = (const float*)d_in[12];
    const float* ln1b  = (const float*)d_in[13];
    const float* W1    = (const float*)d_in[14];
    const float* b1    = (const float*)d_in[15];
    const float* W2    = (const float*)d_in[16];
    const float* b2    = (const float*)d_in[17];
    const float* ln2g  = (const float*)d_in[18];
    const float* ln2b  = (const float*)d_in[19];
    const float* Wh    = (const float*)d_in[20];
    const float* bh    = (const float*)d_in[21];
    float* out = (float*)d_out;

    float *h0, *qkv, *o, *h1, *f, *bqkv;
    __half *h0h, *atth, *h1h, *midh, *h2h;
    __half *Wqkv, *WoT, *W1T, *W2T, *WhT;
    cudaGetSymbolAddress((void**)&h0,   g_h0);
    cudaGetSymbolAddress((void**)&h0h,  g_h0h);
    cudaGetSymbolAddress((void**)&qkv,  g_qkv);
    cudaGetSymbolAddress((void**)&atth, g_atth);
    cudaGetSymbolAddress((void**)&o,    g_o);
    cudaGetSymbolAddress((void**)&h1,   g_h1);
    cudaGetSymbolAddress((void**)&h1h,  g_h1h);
    cudaGetSymbolAddress((void**)&midh, g_midh);
    cudaGetSymbolAddress((void**)&f,    g_f);
    cudaGetSymbolAddress((void**)&h2h,  g_h2h);
    cudaGetSymbolAddress((void**)&Wqkv, g_Wqkv);
    cudaGetSymbolAddress((void**)&WoT,  g_WoT);
    cudaGetSymbolAddress((void**)&W1T,  g_W1T);
    cudaGetSymbolAddress((void**)&W2T,  g_W2T);
    cudaGetSymbolAddress((void**)&WhT,  g_WhT);
    cudaGetSymbolAddress((void**)&bqkv, g_bqkv);

    const int GEMM_SMEM = STAGES * (STAGE_AB + STAGE_BB);  // 98304 bytes
    static int attr_set = 0;
    if (!attr_set) {
        cudaFuncSetAttribute(gemm_tc, cudaFuncAttributeMaxDynamicSharedMemorySize, GEMM_SMEM);
        attr_set = 1;
    }

    dim3 tb(32, 8);

    // 0: embed (+ bias concat in tail blocks)
    embed_kernel<<<NTOK + 12, 128>>>(x, tab, rowe, cole, bq, bk, bv, h0, h0h, bqkv);
    // 1: fused QKV weight transpose
    qkv_transpose<<<dim3(16, 16, 3), tb>>>(Wq, Wk, Wv, Wqkv);
    // 2: Wo transpose
    transpose_h<<<dim3(16, 16), tb>>>(Wo, WoT, D, D);
    // 3: fused QKV GEMM (profiled)
    gemm_tc<<<dim3(3 * D / GBN, NTOK / GBM), NTHR, GEMM_SMEM>>>(
        h0h, Wqkv, bqkv, qkv, nullptr, NTOK, 3 * D, D, 0);

    // remaining weight transposes
    transpose_h<<<dim3(DFF / 32,   D / 32),   tb>>>(W1, W1T, D,   DFF);
    transpose_h<<<dim3(D / 32,     DFF / 32), tb>>>(W2, W2T, DFF, D);
    transpose_h<<<dim3(VOCAB / 32, D / 32),   tb>>>(Wh, WhT, D,   VOCAB);

    // attention
    attn_kernel<<<NTOK, 128>>>(qkv, atth);

    // O projection
    gemm_tc<<<dim3(D / GBN, NTOK / GBM), NTHR, GEMM_SMEM>>>(
        atth, WoT, bo, o, nullptr, NTOK, D, D, 0);

    // residual + LN1 (fp32 for residual, fp16 for FFN1)
    add_ln_kernel<<<NTOK, 128>>>(h0, o, ln1g, ln1b, h1, h1h);

    // FFN
    gemm_tc<<<dim3(DFF / GBN, NTOK / GBM), NTHR, GEMM_SMEM>>>(
        h1h, W1T, b1, nullptr, midh, NTOK, DFF, D, 1);
    gemm_tc<<<dim3(D / GBN, NTOK / GBM), NTHR, GEMM_SMEM>>>(
        midh, W2T, b2, f, nullptr, NTOK, D, DFF, 0);

    // residual + LN2 (fp16 only; only the head consumes it)
    add_ln_kernel<<<NTOK, 128>>>(h1, f, ln2g, ln2b, nullptr, h2h);

    // vocab head -> d_out
    gemm_tc<<<dim3(VOCAB / GBN, NTOK / GBM), NTHR, GEMM_SMEM>>>(
        h2h, WhT, bh, out, nullptr, NTOK, VOCAB, D, 0);
}